// round 8
// baseline (speedup 1.0000x reference)
#include <cuda_runtime.h>
#include <math.h>

#define BB 64
#define SS 512
#define FF 512
#define HH 1024
#define G3 3072
#define NBLOCKS 256
#define NT 512
#define WSM_FLOATS (1024 * 24)      // resident W slice: [k=1024][24 gate-cols]
#define SCR_STRIDE 14               // reduction scratch stride (floats), 8B aligned
#define HT_BUF 65536                // 1024*64 floats per hT phase buffer
#define NGROUPS 16

// Scratch: input-side gates gx = x @ W_ih + bias : [B*S, 3H] fp32
__device__ float g_gx[(size_t)BB * SS * G3];
// Transposed h mirror, double-buffered: g_hT[t&1][j (1024)][b (64)]
__device__ float g_hT[2 * HT_BUF];

// Two-level grid barrier (monotonic counters — replay-safe, no reset needed)
__device__ unsigned int g_cnt[NGROUPS * 32];   // one counter per 128B
__device__ unsigned int g_root = 0;
__device__ volatile unsigned int g_gen = 0;

typedef unsigned long long u64t;

// ---------------- f32x2 packed helpers ----------------
__device__ __forceinline__ u64t pack2(float lo, float hi) {
    u64t r; asm("mov.b64 %0, {%1, %2};" : "=l"(r) : "f"(lo), "f"(hi)); return r;
}
__device__ __forceinline__ void unpack2(u64t v, float& lo, float& hi) {
    asm("mov.b64 {%0, %1}, %2;" : "=f"(lo), "=f"(hi) : "l"(v));
}
__device__ __forceinline__ void fma2(u64t& d, u64t a, u64t b) {
    asm("fma.rn.f32x2 %0, %1, %2, %0;" : "+l"(d) : "l"(a), "l"(b));
}
__device__ __forceinline__ u64t add2(u64t a, u64t b) {
    u64t r; asm("add.rn.f32x2 %0, %1, %2;" : "=l"(r) : "l"(a), "l"(b)); return r;
}

// ---------------- cp.async helpers ----------------
__device__ __forceinline__ void cp16(unsigned int dst, const void* src) {
    asm volatile("cp.async.ca.shared.global [%0], [%1], 16;" :: "r"(dst), "l"(src) : "memory");
}
__device__ __forceinline__ void cp_commit() { asm volatile("cp.async.commit_group;" ::: "memory"); }
template<int N> __device__ __forceinline__ void cp_wait() {
    asm volatile("cp.async.wait_group %0;" :: "n"(N) : "memory");
}
__device__ __forceinline__ unsigned int smem_u32(const void* p) {
    return (unsigned int)__cvta_generic_to_shared(p);
}

__device__ __forceinline__ float gate_fn(float az, float ar, float ge, float ae, float ho) {
    float z   = 1.0f / (1.0f + expf(-az));
    float r   = 1.0f / (1.0f + expf(-ar));
    float eta = tanhf(ge + r * tanhf(ae));
    return z * ho + (1.0f - z) * eta;
}

// ---------------------------------------------------------------------------
// Kernel 1: input GEMM  g_gx = x @ W_ih + bias.  M=32768, K=512, N=3072.
// ---------------------------------------------------------------------------
__global__ __launch_bounds__(256, 2) void gemm_ih(const float* __restrict__ A,
                                                  const float* __restrict__ Bw,
                                                  const float* __restrict__ bias) {
    __shared__ float As[16][132];
    __shared__ float Bs[16][128];

    const int K = FF, N = G3;
    const int bm = blockIdx.y * 128;
    const int bn = blockIdx.x * 128;
    const int tid = threadIdx.x;
    const int tr = tid >> 4;
    const int tc = tid & 15;

    u64t acc2[8][4];
#pragma unroll
    for (int i = 0; i < 8; ++i)
#pragma unroll
        for (int j = 0; j < 4; ++j) acc2[i][j] = 0ULL;

    for (int k0 = 0; k0 < K; k0 += 16) {
#pragma unroll
        for (int i = 0; i < 2; ++i) {
            int f = tid + i * 256;
            int ar = f >> 2, ac4 = f & 3;
            float4 av = *(const float4*)(A + (size_t)(bm + ar) * K + k0 + ac4 * 4);
            As[ac4 * 4 + 0][ar] = av.x;
            As[ac4 * 4 + 1][ar] = av.y;
            As[ac4 * 4 + 2][ar] = av.z;
            As[ac4 * 4 + 3][ar] = av.w;
            int br = f >> 5, bc4 = f & 31;
            *(float4*)(&Bs[br][bc4 * 4]) =
                *(const float4*)(Bw + (size_t)(k0 + br) * N + bn + bc4 * 4);
        }
        __syncthreads();
#pragma unroll
        for (int kk = 0; kk < 16; ++kk) {
            float a[8];
            *(float4*)(a)     = *(const float4*)(&As[kk][tr * 8]);
            *(float4*)(a + 4) = *(const float4*)(&As[kk][tr * 8 + 4]);
            ulonglong2 bq0 = *(const ulonglong2*)(&Bs[kk][tc * 8]);
            ulonglong2 bq1 = *(const ulonglong2*)(&Bs[kk][tc * 8 + 4]);
#pragma unroll
            for (int i = 0; i < 8; ++i) {
                u64t ai = pack2(a[i], a[i]);
                fma2(acc2[i][0], ai, bq0.x);
                fma2(acc2[i][1], ai, bq0.y);
                fma2(acc2[i][2], ai, bq1.x);
                fma2(acc2[i][3], ai, bq1.y);
            }
        }
        __syncthreads();
    }

#pragma unroll
    for (int i = 0; i < 8; ++i) {
        int row = bm + tr * 8 + i;
        float o[8];
        unpack2(acc2[i][0], o[0], o[1]);
        unpack2(acc2[i][1], o[2], o[3]);
        unpack2(acc2[i][2], o[4], o[5]);
        unpack2(acc2[i][3], o[6], o[7]);
#pragma unroll
        for (int j = 0; j < 8; j += 4) {
            int col = bn + tc * 8 + j;
            float4 bv = *(const float4*)(bias + col);
            float4 ov;
            ov.x = o[j + 0] + bv.x;
            ov.y = o[j + 1] + bv.y;
            ov.z = o[j + 2] + bv.z;
            ov.w = o[j + 3] + bv.w;
            *(float4*)(g_gx + (size_t)row * N + col) = ov;
        }
    }
}

// ---------------------------------------------------------------------------
// Kernel 2: persistent GRU scan. 256 CTAs (2/SM) x 512 threads, 512 steps.
//   CTA tile: 32 batch rows x 8 hidden cols. W slice [1024 x 24] resident.
//   Thread tile: 2 rows x 2 cols/gate x 128 k (8-way K split). f32x2 FMA.
//   Two-level grid barrier; hov & h_last carried in registers.
// ---------------------------------------------------------------------------
__global__ __launch_bounds__(NT, 2) void gru_scan(const float* __restrict__ whh,
                                                  float* __restrict__ out) {
    extern __shared__ float smem[];
    float* wsm = smem;                 // [1024][24]
    float* scr = smem + WSM_FLOATS;    // [4][64][SCR_STRIDE]

    const int bid = blockIdx.x;
    const int mt = bid >> 7;                // 0..1   batch half (32 rows)
    const int jt = bid & 127;               // 0..127 hidden col tile (8 cols)
    const int m0 = mt * 32;
    const int jbase = jt * 8;
    const int tid = threadIdx.x;
    const int kq = tid >> 6;                // 0..7 K octant (128 k each)
    const int local = tid & 63;
    const int mp = local & 15;              // rows 2mp, 2mp+1 (of 32)
    const int jq = local >> 4;              // 0..3 -> cols {2jq, 2jq+1} per gate
    const int gid = bid & (NGROUPS - 1);

    const unsigned int base_gen = g_gen;    // read before any arrival (see barrier)

    // ---- one-time W_hh slice load: whh[k][g*1024 + jbase + c] -> wsm[k][g*8 + c]
    {
        const unsigned int wsu = smem_u32(wsm);
#pragma unroll
        for (int i = 0; i < 12; ++i) {
            int idx = tid + NT * i;              // 0..6143
            int k = idx / 6;
            int sub = idx - k * 6;               // 0..5
            cp16(wsu + (unsigned)(k * 24 + sub * 4) * 4u,
                 whh + (size_t)k * G3 + (sub >> 1) * HH + jbase + (sub & 1) * 4);
        }
        cp_commit();
        cp_wait<0>();
        __syncthreads();
    }

    // gate-phase mapping (tid < 256): one output per thread
    const int gm = tid >> 3;                // 0..31 local row
    const int gj = tid & 7;                 // 0..7  local col
    const int glocal = (gj >> 1) * 16 + (gm >> 1);
    const int gofs = (gm & 1) * 6 + (gj & 1);

    float gz = 0.0f, grv = 0.0f, gev = 0.0f, hprev = 0.0f;
    if (tid < 256) {
        const float* gp = g_gx + ((size_t)(m0 + gm) * SS + 0) * G3 + jbase + gj;
        gz = gp[0]; grv = gp[HH]; gev = gp[2 * HH];
    }

    u64t acc[6];

    for (int t = 0; t < SS; ++t) {
        if (t > 0) {
            const float* hb = g_hT + (size_t)((t - 1) & 1) * HT_BUF + m0 + 2 * mp;
#pragma unroll
            for (int i = 0; i < 6; ++i) acc[i] = 0ULL;

            float2 hbuf[2][4];
#pragma unroll
            for (int i = 0; i < 4; ++i)
                hbuf[0][i] = *(const float2*)(hb + (size_t)(kq * 128 + i) * 64);

#pragma unroll 2
            for (int kb = 0; kb < 128; kb += 4) {
                const int cur = (kb >> 2) & 1, nxt = cur ^ 1;
                if (kb < 124) {
#pragma unroll
                    for (int i = 0; i < 4; ++i)
                        hbuf[nxt][i] =
                            *(const float2*)(hb + (size_t)(kq * 128 + kb + 4 + i) * 64);
                }
#pragma unroll
                for (int i = 0; i < 4; ++i) {
                    const float* wp = wsm + (kq * 128 + kb + i) * 24 + jq * 2;
                    u64t wz = *(const u64t*)(wp);
                    u64t wr = *(const u64t*)(wp + 8);
                    u64t we = *(const u64t*)(wp + 16);
                    float2 h = hbuf[cur][i];
                    u64t h0 = pack2(h.x, h.x);
                    u64t h1 = pack2(h.y, h.y);
                    fma2(acc[0], h0, wz); fma2(acc[1], h0, wr); fma2(acc[2], h0, we);
                    fma2(acc[3], h1, wz); fma2(acc[4], h1, wr); fma2(acc[5], h1, we);
                }
            }

            // stage 1: upper octants write packed partials
            if (kq >= 4) {
                float* p = scr + (size_t)((kq - 4) * 64 + local) * SCR_STRIDE;
#pragma unroll
                for (int i = 0; i < 6; ++i) *(u64t*)(p + 2 * i) = acc[i];
            }
        }
        __syncthreads();
        if (t > 0 && kq < 4) {   // stage 2: lower octants add in place (f32x2)
            float* p = scr + (size_t)(kq * 64 + local) * SCR_STRIDE;
#pragma unroll
            for (int i = 0; i < 6; ++i)
                *(u64t*)(p + 2 * i) = add2(*(const u64t*)(p + 2 * i), acc[i]);
        }
        __syncthreads();

        // ---- gate phase: one output per thread (tid < 256) ----
        if (tid < 256) {
            float sz = 0.0f, sr = 0.0f, se = 0.0f;
            if (t > 0) {
#pragma unroll
                for (int q = 0; q < 4; ++q) {
                    const float* p = scr + (size_t)(q * 64 + glocal) * SCR_STRIDE + gofs;
                    sz += p[0];
                    sr += p[2];
                    se += p[4];
                }
            }
            float hn = gate_fn(gz + sz, grv + sr, gev, se, hprev);
            hprev = hn;
            out[((size_t)(m0 + gm) * SS + t) * HH + jbase + gj] = hn;
            g_hT[(size_t)(t & 1) * HT_BUF + (size_t)(jbase + gj) * 64 + m0 + gm] = hn;
        }

        // ---- two-level grid barrier: arrive early, prefetch, poll late ----
        __syncthreads();
        if (tid == 0) {
            __threadfence();
            unsigned int o1 = atomicAdd(&g_cnt[gid * 32], 1u);
            if ((o1 & 15u) == 15u) {
                unsigned int o2 = atomicAdd(&g_root, 1u);
                if ((o2 & 15u) == 15u) {
                    __threadfence();
                    atomicAdd((unsigned int*)&g_gen, 1u);
                }
            }
        }
        if (tid < 256 && t + 1 < SS) {      // hide barrier latency with gx prefetch
            const float* gp = g_gx + ((size_t)(m0 + gm) * SS + (t + 1)) * G3 + jbase + gj;
            gz = gp[0]; grv = gp[HH]; gev = gp[2 * HH];
        }
        if (tid == 0) {
            const unsigned int want = base_gen + (unsigned int)t + 1u;
            while (g_gen < want) { __nanosleep(32); }
            __threadfence();
        }
        __syncthreads();
    }

    // h_last straight from registers
    if (tid < 256)
        out[(size_t)BB * SS * HH + (size_t)(m0 + gm) * HH + jbase + gj] = hprev;
}

// ---------------------------------------------------------------------------
extern "C" void kernel_launch(void* const* d_in, const int* in_sizes, int n_in,
                              void* d_out, int out_size) {
    const float* x    = (const float*)d_in[0];  // [64,512,512]
    const float* wih  = (const float*)d_in[1];  // [512,3072]
    const float* whh  = (const float*)d_in[2];  // [1024,3072]
    const float* bias = (const float*)d_in[3];  // [3072]
    float* out = (float*)d_out;

    (void)in_sizes; (void)n_in; (void)out_size;

    dim3 g1(G3 / 128, (BB * SS) / 128);
    gemm_ih<<<g1, 256>>>(x, wih, bias);

    const int scan_smem = (WSM_FLOATS + 4 * 64 * SCR_STRIDE) * (int)sizeof(float); // 112640 B
    cudaFuncSetAttribute(gru_scan, cudaFuncAttributeMaxDynamicSharedMemorySize, scan_smem);
    gru_scan<<<NBLOCKS, NT, scan_smem>>>(whh, out);
}

// round 10
// speedup vs baseline: 1.0780x; 1.0780x over previous
#include <cuda_runtime.h>
#include <math.h>

#define BB 64
#define SS 512
#define FF 512
#define HH 1024
#define G3 3072
#define NBLOCKS 256
#define NT 512
#define WSM_FLOATS (1024 * 24)      // resident W slice: [k=1024][24 gate-cols]
#define SCR_FLOATS (4 * 12 * 64)    // 4 slots x 12 u64 x 32 lanes (f32x2 packed)
#define HT_BUF 65536                // 1024*64 floats per hT phase buffer
#define NGROUPS 16

// Scratch: input-side gates gx = x @ W_ih + bias : [B*S, 3H] fp32
__device__ float g_gx[(size_t)BB * SS * G3];
// Transposed h mirror, double-buffered: g_hT[t&1][j (1024)][b (64)]
__device__ float g_hT[2 * HT_BUF];

// Two-level grid barrier (monotonic counters — replay-safe, no reset needed)
__device__ unsigned int g_cnt[NGROUPS * 32];   // one counter per 128B
__device__ unsigned int g_root = 0;
__device__ volatile unsigned int g_gen = 0;

typedef unsigned long long u64t;

// ---------------- f32x2 packed helpers ----------------
__device__ __forceinline__ u64t pack2(float lo, float hi) {
    u64t r; asm("mov.b64 %0, {%1, %2};" : "=l"(r) : "f"(lo), "f"(hi)); return r;
}
__device__ __forceinline__ void unpack2(u64t v, float& lo, float& hi) {
    asm("mov.b64 {%0, %1}, %2;" : "=f"(lo), "=f"(hi) : "l"(v));
}
__device__ __forceinline__ void fma2(u64t& d, u64t a, u64t b) {
    asm("fma.rn.f32x2 %0, %1, %2, %0;" : "+l"(d) : "l"(a), "l"(b));
}
__device__ __forceinline__ u64t add2(u64t a, u64t b) {
    u64t r; asm("add.rn.f32x2 %0, %1, %2;" : "=l"(r) : "l"(a), "l"(b)); return r;
}

// ---------------- cp.async helpers ----------------
__device__ __forceinline__ void cp16(unsigned int dst, const void* src) {
    asm volatile("cp.async.ca.shared.global [%0], [%1], 16;" :: "r"(dst), "l"(src) : "memory");
}
__device__ __forceinline__ void cp_commit() { asm volatile("cp.async.commit_group;" ::: "memory"); }
template<int N> __device__ __forceinline__ void cp_wait() {
    asm volatile("cp.async.wait_group %0;" :: "n"(N) : "memory");
}
__device__ __forceinline__ unsigned int smem_u32(const void* p) {
    return (unsigned int)__cvta_generic_to_shared(p);
}

__device__ __forceinline__ float gate_fn(float az, float ar, float ge, float ae, float ho) {
    float z   = 1.0f / (1.0f + expf(-az));
    float r   = 1.0f / (1.0f + expf(-ar));
    float eta = tanhf(ge + r * tanhf(ae));
    return z * ho + (1.0f - z) * eta;
}

// ---------------------------------------------------------------------------
// Kernel 1: input GEMM  g_gx = x @ W_ih + bias.  M=32768, K=512, N=3072.
// ---------------------------------------------------------------------------
__global__ __launch_bounds__(256, 2) void gemm_ih(const float* __restrict__ A,
                                                  const float* __restrict__ Bw,
                                                  const float* __restrict__ bias) {
    __shared__ float As[16][132];
    __shared__ float Bs[16][128];

    const int K = FF, N = G3;
    const int bm = blockIdx.y * 128;
    const int bn = blockIdx.x * 128;
    const int tid = threadIdx.x;
    const int tr = tid >> 4;
    const int tc = tid & 15;

    u64t acc2[8][4];
#pragma unroll
    for (int i = 0; i < 8; ++i)
#pragma unroll
        for (int j = 0; j < 4; ++j) acc2[i][j] = 0ULL;

    for (int k0 = 0; k0 < K; k0 += 16) {
#pragma unroll
        for (int i = 0; i < 2; ++i) {
            int f = tid + i * 256;
            int ar = f >> 2, ac4 = f & 3;
            float4 av = *(const float4*)(A + (size_t)(bm + ar) * K + k0 + ac4 * 4);
            As[ac4 * 4 + 0][ar] = av.x;
            As[ac4 * 4 + 1][ar] = av.y;
            As[ac4 * 4 + 2][ar] = av.z;
            As[ac4 * 4 + 3][ar] = av.w;
            int br = f >> 5, bc4 = f & 31;
            *(float4*)(&Bs[br][bc4 * 4]) =
                *(const float4*)(Bw + (size_t)(k0 + br) * N + bn + bc4 * 4);
        }
        __syncthreads();
#pragma unroll
        for (int kk = 0; kk < 16; ++kk) {
            float a[8];
            *(float4*)(a)     = *(const float4*)(&As[kk][tr * 8]);
            *(float4*)(a + 4) = *(const float4*)(&As[kk][tr * 8 + 4]);
            ulonglong2 bq0 = *(const ulonglong2*)(&Bs[kk][tc * 8]);
            ulonglong2 bq1 = *(const ulonglong2*)(&Bs[kk][tc * 8 + 4]);
#pragma unroll
            for (int i = 0; i < 8; ++i) {
                u64t ai = pack2(a[i], a[i]);
                fma2(acc2[i][0], ai, bq0.x);
                fma2(acc2[i][1], ai, bq0.y);
                fma2(acc2[i][2], ai, bq1.x);
                fma2(acc2[i][3], ai, bq1.y);
            }
        }
        __syncthreads();
    }

#pragma unroll
    for (int i = 0; i < 8; ++i) {
        int row = bm + tr * 8 + i;
        float o[8];
        unpack2(acc2[i][0], o[0], o[1]);
        unpack2(acc2[i][1], o[2], o[3]);
        unpack2(acc2[i][2], o[4], o[5]);
        unpack2(acc2[i][3], o[6], o[7]);
#pragma unroll
        for (int j = 0; j < 8; j += 4) {
            int col = bn + tc * 8 + j;
            float4 bv = *(const float4*)(bias + col);
            float4 ov;
            ov.x = o[j + 0] + bv.x;
            ov.y = o[j + 1] + bv.y;
            ov.z = o[j + 2] + bv.z;
            ov.w = o[j + 3] + bv.w;
            *(float4*)(g_gx + (size_t)row * N + col) = ov;
        }
    }
}

// ---------------------------------------------------------------------------
// Kernel 2: persistent GRU scan. 256 CTAs (2/SM) x 512 threads, 512 steps.
//   CTA tile: 32 batch rows x 8 hidden cols. W slice [1024 x 24] resident.
//   Thread tile: 4 rows x 2 cols/gate x 64 k (16-way K split). f32x2 FMA.
//   4-slot swizzled scratch, 4-phase warp-owned reduction.
// ---------------------------------------------------------------------------
__global__ __launch_bounds__(NT, 2) void gru_scan(const float* __restrict__ whh,
                                                  float* __restrict__ out) {
    extern __shared__ float smem[];
    float* wsm = smem;                 // [1024][24]
    float* scr = smem + WSM_FLOATS;    // 4 slots x 12 u64 x 32 lanes, swizzled

    const int bid = blockIdx.x;
    const int mt = bid >> 7;                // 0..1   batch half (32 rows)
    const int jt = bid & 127;               // 0..127 hidden col tile (8 cols)
    const int m0 = mt * 32;
    const int jbase = jt * 8;
    const int tid = threadIdx.x;
    const int kq = tid >> 5;                // 0..15 K sixteenth (64 k each)
    const int local = tid & 31;
    const int mp = local & 7;               // rows 4mp..4mp+3 (of 32)
    const int jq = local >> 3;              // 0..3 -> cols {2jq, 2jq+1} per gate
    const int phase = kq >> 2;              // reduction phase 0..3
    const int slot = kq & 3;                // scratch slot 0..3
    const int gid = bid & (NGROUPS - 1);

    const unsigned int base_gen = g_gen;    // read before any arrival

    // ---- one-time W_hh slice load: whh[k][g*1024 + jbase + c] -> wsm[k*24 + g*8 + c]
    {
        const unsigned int wsu = smem_u32(wsm);
#pragma unroll
        for (int i = 0; i < 12; ++i) {
            int idx = tid + NT * i;              // 0..6143
            int k = idx / 6;
            int sub = idx - k * 6;               // 0..5
            cp16(wsu + (unsigned)(k * 24 + sub * 4) * 4u,
                 whh + (size_t)k * G3 + (sub >> 1) * HH + jbase + (sub & 1) * 4);
        }
        cp_commit();
        cp_wait<0>();
        __syncthreads();
    }

    // gate-phase mapping (tid < 256): one output per thread
    const int gm = tid >> 3;                // 0..31 local row
    const int gj = tid & 7;                 // 0..7  local col
    const int glocal = (gj >> 1) * 8 + (gm >> 2);
    const int grr = gm & 3;                 // row within owner thread
    const int gcc = gj & 1;                 // col within pair

    float gz = 0.0f, grv = 0.0f, gev = 0.0f, hprev = 0.0f;
    if (tid < 256) {
        const float* gp = g_gx + ((size_t)(m0 + gm) * SS + 0) * G3 + jbase + gj;
        gz = gp[0]; grv = gp[HH]; gev = gp[2 * HH];
    }

    // scratch base for this thread's slot (float units); swizzled per-u64
    float* myslot = scr + slot * (12 * 64);

    u64t acc[12];

    for (int t = 0; t < SS; ++t) {
        if (t > 0) {
            // h rows 4mp..4mp+3 at column k: one 128B line per warp-LDG
            const float* hb = g_hT + (size_t)((t - 1) & 1) * HT_BUF
                            + (size_t)(kq * 64) * 64 + m0 + 4 * mp;
#pragma unroll
            for (int i = 0; i < 12; ++i) acc[i] = 0ULL;

            float4 hbuf[2];
            hbuf[0] = *(const float4*)(hb);

#pragma unroll 4
            for (int kb = 0; kb < 64; ++kb) {
                const int cur = kb & 1;
                if (kb < 63)
                    hbuf[cur ^ 1] = *(const float4*)(hb + (size_t)(kb + 1) * 64);
                const float* wp = wsm + (kq * 64 + kb) * 24 + jq * 2;
                u64t wz = *(const u64t*)(wp);
                u64t wr = *(const u64t*)(wp + 8);
                u64t we = *(const u64t*)(wp + 16);
                float4 h = hbuf[cur];
                u64t h0 = pack2(h.x, h.x);
                u64t h1 = pack2(h.y, h.y);
                u64t h2 = pack2(h.z, h.z);
                u64t h3 = pack2(h.w, h.w);
                fma2(acc[0], h0, wz);  fma2(acc[1], h0, wr);  fma2(acc[2], h0, we);
                fma2(acc[3], h1, wz);  fma2(acc[4], h1, wr);  fma2(acc[5], h1, we);
                fma2(acc[6], h2, wz);  fma2(acc[7], h2, wr);  fma2(acc[8], h2, we);
                fma2(acc[9], h3, wz);  fma2(acc[10], h3, wr); fma2(acc[11], h3, we);
            }

            // ---- 4-phase warp-owned reduction into 4 slots ----
            if (phase == 3) {
#pragma unroll
                for (int i = 0; i < 12; ++i) {
                    int off = i * 64 + ((local * 2) ^ ((i & 3) << 3));
                    *(u64t*)(myslot + off) = acc[i];
                }
            }
        }
        __syncthreads();
        if (t > 0 && phase == 2) {
#pragma unroll
            for (int i = 0; i < 12; ++i) {
                int off = i * 64 + ((local * 2) ^ ((i & 3) << 3));
                *(u64t*)(myslot + off) = add2(*(const u64t*)(myslot + off), acc[i]);
            }
        }
        __syncthreads();
        if (t > 0 && phase == 1) {
#pragma unroll
            for (int i = 0; i < 12; ++i) {
                int off = i * 64 + ((local * 2) ^ ((i & 3) << 3));
                *(u64t*)(myslot + off) = add2(*(const u64t*)(myslot + off), acc[i]);
            }
        }
        __syncthreads();
        if (t > 0 && phase == 0) {
#pragma unroll
            for (int i = 0; i < 12; ++i) {
                int off = i * 64 + ((local * 2) ^ ((i & 3) << 3));
                *(u64t*)(myslot + off) = add2(*(const u64t*)(myslot + off), acc[i]);
            }
        }
        __syncthreads();

        // ---- gate phase: one output per thread (tid < 256) ----
        if (tid < 256) {
            float sz = 0.0f, sr = 0.0f, se = 0.0f;
            if (t > 0) {
#pragma unroll
                for (int s = 0; s < 4; ++s) {
                    const float* sb = scr + s * (12 * 64);
                    int i0 = grr * 3;
                    sz += sb[(i0 + 0) * 64 + (((glocal * 2) ^ (((i0 + 0) & 3) << 3)) + gcc)];
                    sr += sb[(i0 + 1) * 64 + (((glocal * 2) ^ (((i0 + 1) & 3) << 3)) + gcc)];
                    se += sb[(i0 + 2) * 64 + (((glocal * 2) ^ (((i0 + 2) & 3) << 3)) + gcc)];
                }
            }
            float hn = gate_fn(gz + sz, grv + sr, gev, se, hprev);
            hprev = hn;
            out[((size_t)(m0 + gm) * SS + t) * HH + jbase + gj] = hn;
            g_hT[(size_t)(t & 1) * HT_BUF + (size_t)(jbase + gj) * 64 + m0 + gm] = hn;
        }

        // ---- two-level grid barrier: arrive early, prefetch, poll late ----
        __syncthreads();
        if (tid == 0) {
            __threadfence();
            unsigned int o1 = atomicAdd(&g_cnt[gid * 32], 1u);
            if ((o1 & 15u) == 15u) {
                unsigned int o2 = atomicAdd(&g_root, 1u);
                if ((o2 & 15u) == 15u) {
                    __threadfence();
                    atomicAdd((unsigned int*)&g_gen, 1u);
                }
            }
        }
        if (tid < 256 && t + 1 < SS) {      // hide barrier latency with gx prefetch
            const float* gp = g_gx + ((size_t)(m0 + gm) * SS + (t + 1)) * G3 + jbase + gj;
            gz = gp[0]; grv = gp[HH]; gev = gp[2 * HH];
        }
        if (tid == 0) {
            const unsigned int want = base_gen + (unsigned int)t + 1u;
            while (g_gen < want) { __nanosleep(32); }
            __threadfence();
        }
        __syncthreads();
    }

    // h_last straight from registers
    if (tid < 256)
        out[(size_t)BB * SS * HH + (size_t)(m0 + gm) * HH + jbase + gj] = hprev;
}

// ---------------------------------------------------------------------------
extern "C" void kernel_launch(void* const* d_in, const int* in_sizes, int n_in,
                              void* d_out, int out_size) {
    const float* x    = (const float*)d_in[0];  // [64,512,512]
    const float* wih  = (const float*)d_in[1];  // [512,3072]
    const float* whh  = (const float*)d_in[2];  // [1024,3072]
    const float* bias = (const float*)d_in[3];  // [3072]
    float* out = (float*)d_out;

    (void)in_sizes; (void)n_in; (void)out_size;

    dim3 g1(G3 / 128, (BB * SS) / 128);
    gemm_ih<<<g1, 256>>>(x, wih, bias);

    const int scan_smem = (WSM_FLOATS + SCR_FLOATS) * (int)sizeof(float); // 110592 B
    cudaFuncSetAttribute(gru_scan, cudaFuncAttributeMaxDynamicSharedMemorySize, scan_smem);
    gru_scan<<<NBLOCKS, NT, scan_smem>>>(whh, out);
}

// round 12
// speedup vs baseline: 1.1028x; 1.0230x over previous
#include <cuda_runtime.h>
#include <math.h>

#define BB 64
#define SS 512
#define FF 512
#define HH 1024
#define G3 3072
#define NBLOCKS 128
#define NT 1024
#define WSM_FLOATS (1024 * 48)      // resident W slice: [k=1024][48 gate-cols]
#define SCR_FLOATS (4 * 12 * 128)   // 4 slots x 12 u64 x 64 lanes (f32x2 packed)
#define HT_BUF 65536                // 1024*64 floats per hT phase buffer
#define NGROUPS 16

// Scratch: input-side gates gx = x @ W_ih + bias : [B*S, 3H] fp32
__device__ float g_gx[(size_t)BB * SS * G3];
// Transposed h mirror, double-buffered: g_hT[t&1][j (1024)][b (64)]
__device__ float g_hT[2 * HT_BUF];

// Two-level grid barrier (monotonic counters — replay-safe, no reset needed)
__device__ unsigned int g_cnt[NGROUPS * 32];   // one counter per 128B
__device__ unsigned int g_root = 0;
__device__ volatile unsigned int g_gen = 0;

typedef unsigned long long u64t;

// ---------------- f32x2 packed helpers ----------------
__device__ __forceinline__ u64t pack2(float lo, float hi) {
    u64t r; asm("mov.b64 %0, {%1, %2};" : "=l"(r) : "f"(lo), "f"(hi)); return r;
}
__device__ __forceinline__ void unpack2(u64t v, float& lo, float& hi) {
    asm("mov.b64 {%0, %1}, %2;" : "=f"(lo), "=f"(hi) : "l"(v));
}
__device__ __forceinline__ void fma2(u64t& d, u64t a, u64t b) {
    asm("fma.rn.f32x2 %0, %1, %2, %0;" : "+l"(d) : "l"(a), "l"(b));
}
__device__ __forceinline__ u64t add2(u64t a, u64t b) {
    u64t r; asm("add.rn.f32x2 %0, %1, %2;" : "=l"(r) : "l"(a), "l"(b)); return r;
}

// ---------------- cp.async helpers ----------------
__device__ __forceinline__ void cp16(unsigned int dst, const void* src) {
    asm volatile("cp.async.ca.shared.global [%0], [%1], 16;" :: "r"(dst), "l"(src) : "memory");
}
__device__ __forceinline__ void cp_commit() { asm volatile("cp.async.commit_group;" ::: "memory"); }
template<int N> __device__ __forceinline__ void cp_wait() {
    asm volatile("cp.async.wait_group %0;" :: "n"(N) : "memory");
}
__device__ __forceinline__ unsigned int smem_u32(const void* p) {
    return (unsigned int)__cvta_generic_to_shared(p);
}

__device__ __forceinline__ float gate_fn(float az, float ar, float ge, float ae, float ho) {
    float z   = 1.0f / (1.0f + expf(-az));
    float r   = 1.0f / (1.0f + expf(-ar));
    float eta = tanhf(ge + r * tanhf(ae));
    return z * ho + (1.0f - z) * eta;
}

// ---------------------------------------------------------------------------
// Kernel 1: input GEMM  g_gx = x @ W_ih + bias.  M=32768, K=512, N=3072.
// ---------------------------------------------------------------------------
__global__ __launch_bounds__(256, 2) void gemm_ih(const float* __restrict__ A,
                                                  const float* __restrict__ Bw,
                                                  const float* __restrict__ bias) {
    __shared__ float As[16][132];
    __shared__ float Bs[16][128];

    const int K = FF, N = G3;
    const int bm = blockIdx.y * 128;
    const int bn = blockIdx.x * 128;
    const int tid = threadIdx.x;
    const int tr = tid >> 4;
    const int tc = tid & 15;

    u64t acc2[8][4];
#pragma unroll
    for (int i = 0; i < 8; ++i)
#pragma unroll
        for (int j = 0; j < 4; ++j) acc2[i][j] = 0ULL;

    for (int k0 = 0; k0 < K; k0 += 16) {
#pragma unroll
        for (int i = 0; i < 2; ++i) {
            int f = tid + i * 256;
            int ar = f >> 2, ac4 = f & 3;
            float4 av = *(const float4*)(A + (size_t)(bm + ar) * K + k0 + ac4 * 4);
            As[ac4 * 4 + 0][ar] = av.x;
            As[ac4 * 4 + 1][ar] = av.y;
            As[ac4 * 4 + 2][ar] = av.z;
            As[ac4 * 4 + 3][ar] = av.w;
            int br = f >> 5, bc4 = f & 31;
            *(float4*)(&Bs[br][bc4 * 4]) =
                *(const float4*)(Bw + (size_t)(k0 + br) * N + bn + bc4 * 4);
        }
        __syncthreads();
#pragma unroll
        for (int kk = 0; kk < 16; ++kk) {
            float a[8];
            *(float4*)(a)     = *(const float4*)(&As[kk][tr * 8]);
            *(float4*)(a + 4) = *(const float4*)(&As[kk][tr * 8 + 4]);
            ulonglong2 bq0 = *(const ulonglong2*)(&Bs[kk][tc * 8]);
            ulonglong2 bq1 = *(const ulonglong2*)(&Bs[kk][tc * 8 + 4]);
#pragma unroll
            for (int i = 0; i < 8; ++i) {
                u64t ai = pack2(a[i], a[i]);
                fma2(acc2[i][0], ai, bq0.x);
                fma2(acc2[i][1], ai, bq0.y);
                fma2(acc2[i][2], ai, bq1.x);
                fma2(acc2[i][3], ai, bq1.y);
            }
        }
        __syncthreads();
    }

#pragma unroll
    for (int i = 0; i < 8; ++i) {
        int row = bm + tr * 8 + i;
        float o[8];
        unpack2(acc2[i][0], o[0], o[1]);
        unpack2(acc2[i][1], o[2], o[3]);
        unpack2(acc2[i][2], o[4], o[5]);
        unpack2(acc2[i][3], o[6], o[7]);
#pragma unroll
        for (int j = 0; j < 8; j += 4) {
            int col = bn + tc * 8 + j;
            float4 bv = *(const float4*)(bias + col);
            float4 ov;
            ov.x = o[j + 0] + bv.x;
            ov.y = o[j + 1] + bv.y;
            ov.z = o[j + 2] + bv.z;
            ov.w = o[j + 3] + bv.w;
            *(float4*)(g_gx + (size_t)row * N + col) = ov;
        }
    }
}

// ---------------------------------------------------------------------------
// Kernel 2: persistent GRU scan. 128 CTAs (1/SM) x 1024 threads, 512 steps.
//   CTA tile: 32 batch rows x 16 hidden cols. W slice [1024 x 48] resident.
//   Thread tile: 4 rows x 2 cols/gate x 64 k (16-way K split). f32x2 FMA.
//   4-slot swizzled scratch, 4-phase reduction (64-lane groups).
// ---------------------------------------------------------------------------
__global__ __launch_bounds__(NT, 1) void gru_scan(const float* __restrict__ whh,
                                                  float* __restrict__ out) {
    extern __shared__ float smem[];
    float* wsm = smem;                 // [1024][48]
    float* scr = smem + WSM_FLOATS;    // 4 slots x 12 u64 x 64 lanes, swizzled

    const int bid = blockIdx.x;
    const int mt = bid >> 6;                // 0..1  batch half (32 rows)
    const int jt = bid & 63;                // 0..63 hidden col tile (16 cols)
    const int m0 = mt * 32;
    const int jbase = jt * 16;
    const int tid = threadIdx.x;
    const int kq = tid >> 6;                // 0..15 K sixteenth (64 k each)
    const int local = tid & 63;
    const int mp = local & 7;               // rows 4mp..4mp+3 (of 32)
    const int jq = local >> 3;              // 0..7 -> cols {2jq, 2jq+1} per gate
    const int phase = kq >> 2;              // reduction phase 0..3
    const int slot = kq & 3;                // scratch slot 0..3
    const int gid = bid & (NGROUPS - 1);

    const unsigned int base_gen = g_gen;    // read before any arrival

    // ---- one-time W_hh slice load: whh[k][g*1024 + jbase + c] -> wsm[k*48 + g*16 + c]
    {
        const unsigned int wsu = smem_u32(wsm);
#pragma unroll
        for (int i = 0; i < 12; ++i) {
            int idx = tid + NT * i;              // 0..12287
            int k = idx / 12;
            int sub = idx - k * 12;              // 0..11
            int g = sub >> 2, c4 = sub & 3;
            cp16(wsu + (unsigned)(k * 48 + g * 16 + c4 * 4) * 4u,
                 whh + (size_t)k * G3 + g * HH + jbase + c4 * 4);
        }
        cp_commit();
        cp_wait<0>();
        __syncthreads();
    }

    // gate-phase mapping (tid < 512): one output per thread
    const int gm = tid >> 4;                // 0..31 local row
    const int gj = tid & 15;                // 0..15 local col
    const int glocal = (gj >> 1) * 8 + (gm >> 2);
    const int grr = gm & 3;                 // row within owner thread
    const int gcc = gj & 1;                 // col within pair

    float gz = 0.0f, grv = 0.0f, gev = 0.0f, hprev = 0.0f;
    if (tid < 512) {
        const float* gp = g_gx + ((size_t)(m0 + gm) * SS + 0) * G3 + jbase + gj;
        gz = gp[0]; grv = gp[HH]; gev = gp[2 * HH];
    }

    // scratch base for this thread's slot (float units); swizzled per-u64
    float* myslot = scr + slot * (12 * 128);

    u64t acc[12];

    for (int t = 0; t < SS; ++t) {
        if (t > 0) {
            // h rows 4mp..4mp+3 at column k: one 128B line per warp-LDG
            const float* hb = g_hT + (size_t)((t - 1) & 1) * HT_BUF
                            + (size_t)(kq * 64) * 64 + m0 + 4 * mp;
#pragma unroll
            for (int i = 0; i < 12; ++i) acc[i] = 0ULL;

            float4 hbuf[2];
            hbuf[0] = *(const float4*)(hb);

#pragma unroll 4
            for (int kb = 0; kb < 64; ++kb) {
                const int cur = kb & 1;
                if (kb < 63)
                    hbuf[cur ^ 1] = *(const float4*)(hb + (size_t)(kb + 1) * 64);
                const float* wp = wsm + (kq * 64 + kb) * 48 + jq * 2;
                u64t wz = *(const u64t*)(wp);
                u64t wr = *(const u64t*)(wp + 16);
                u64t we = *(const u64t*)(wp + 32);
                float4 h = hbuf[cur];
                u64t h0 = pack2(h.x, h.x);
                u64t h1 = pack2(h.y, h.y);
                u64t h2 = pack2(h.z, h.z);
                u64t h3 = pack2(h.w, h.w);
                fma2(acc[0], h0, wz);  fma2(acc[1], h0, wr);  fma2(acc[2], h0, we);
                fma2(acc[3], h1, wz);  fma2(acc[4], h1, wr);  fma2(acc[5], h1, we);
                fma2(acc[6], h2, wz);  fma2(acc[7], h2, wr);  fma2(acc[8], h2, we);
                fma2(acc[9], h3, wz);  fma2(acc[10], h3, wr); fma2(acc[11], h3, we);
            }

            // ---- 4-phase reduction into 4 slots (64-lane groups) ----
            if (phase == 3) {
#pragma unroll
                for (int i = 0; i < 12; ++i) {
                    int off = i * 128 + ((local * 2) ^ ((i & 3) << 3));
                    *(u64t*)(myslot + off) = acc[i];
                }
            }
        }
        __syncthreads();
        if (t > 0 && phase == 2) {
#pragma unroll
            for (int i = 0; i < 12; ++i) {
                int off = i * 128 + ((local * 2) ^ ((i & 3) << 3));
                *(u64t*)(myslot + off) = add2(*(const u64t*)(myslot + off), acc[i]);
            }
        }
        __syncthreads();
        if (t > 0 && phase == 1) {
#pragma unroll
            for (int i = 0; i < 12; ++i) {
                int off = i * 128 + ((local * 2) ^ ((i & 3) << 3));
                *(u64t*)(myslot + off) = add2(*(const u64t*)(myslot + off), acc[i]);
            }
        }
        __syncthreads();
        if (t > 0 && phase == 0) {
#pragma unroll
            for (int i = 0; i < 12; ++i) {
                int off = i * 128 + ((local * 2) ^ ((i & 3) << 3));
                *(u64t*)(myslot + off) = add2(*(const u64t*)(myslot + off), acc[i]);
            }
        }
        __syncthreads();

        // ---- gate phase: one output per thread (tid < 512) ----
        if (tid < 512) {
            float sz = 0.0f, sr = 0.0f, se = 0.0f;
            if (t > 0) {
#pragma unroll
                for (int s = 0; s < 4; ++s) {
                    const float* sb = scr + s * (12 * 128);
                    int i0 = grr * 3;
                    sz += sb[(i0 + 0) * 128 + (((glocal * 2) ^ (((i0 + 0) & 3) << 3)) + gcc)];
                    sr += sb[(i0 + 1) * 128 + (((glocal * 2) ^ (((i0 + 1) & 3) << 3)) + gcc)];
                    se += sb[(i0 + 2) * 128 + (((glocal * 2) ^ (((i0 + 2) & 3) << 3)) + gcc)];
                }
            }
            float hn = gate_fn(gz + sz, grv + sr, gev, se, hprev);
            hprev = hn;
            out[((size_t)(m0 + gm) * SS + t) * HH + jbase + gj] = hn;
            g_hT[(size_t)(t & 1) * HT_BUF + (size_t)(jbase + gj) * 64 + m0 + gm] = hn;
        }

        // ---- two-level grid barrier: arrive early, prefetch, poll late ----
        __syncthreads();
        if (tid == 0) {
            __threadfence();
            unsigned int o1 = atomicAdd(&g_cnt[gid * 32], 1u);
            if ((o1 & 7u) == 7u) {                   // 8 CTAs per group
                unsigned int o2 = atomicAdd(&g_root, 1u);
                if ((o2 & 15u) == 15u) {             // 16 groups
                    __threadfence();
                    atomicAdd((unsigned int*)&g_gen, 1u);
                }
            }
        }
        if (tid < 512 && t + 1 < SS) {      // hide barrier latency with gx prefetch
            const float* gp = g_gx + ((size_t)(m0 + gm) * SS + (t + 1)) * G3 + jbase + gj;
            gz = gp[0]; grv = gp[HH]; gev = gp[2 * HH];
        }
        if (tid == 0) {
            const unsigned int want = base_gen + (unsigned int)t + 1u;
            while (g_gen < want) { __nanosleep(32); }
            __threadfence();
        }
        __syncthreads();
    }

    // h_last straight from registers
    if (tid < 512)
        out[(size_t)BB * SS * HH + (size_t)(m0 + gm) * HH + jbase + gj] = hprev;
}

// ---------------------------------------------------------------------------
extern "C" void kernel_launch(void* const* d_in, const int* in_sizes, int n_in,
                              void* d_out, int out_size) {
    const float* x    = (const float*)d_in[0];  // [64,512,512]
    const float* wih  = (const float*)d_in[1];  // [512,3072]
    const float* whh  = (const float*)d_in[2];  // [1024,3072]
    const float* bias = (const float*)d_in[3];  // [3072]
    float* out = (float*)d_out;

    (void)in_sizes; (void)n_in; (void)out_size;

    dim3 g1(G3 / 128, (BB * SS) / 128);
    gemm_ih<<<g1, 256>>>(x, wih, bias);

    const int scan_smem = (WSM_FLOATS + SCR_FLOATS) * (int)sizeof(float); // 221184 B
    cudaFuncSetAttribute(gru_scan, cudaFuncAttributeMaxDynamicSharedMemorySize, scan_smem);
    gru_scan<<<NBLOCKS, NT, scan_smem>>>(whh, out);
}